// round 14
// baseline (speedup 1.0000x reference)
#include <cuda_runtime.h>
#include <math.h>

#define B_   2
#define N_   16384
#define M_   4096
#define KG_  32
#define FULL 0xffffffffu

#define G_    8                 // FPS CTAs per cluster (one cluster per batch)
#define TCC   256               // threads per FPS CTA
#define CHUNK (N_ / G_)         // 2048 points per CTA
#define PPTC  (CHUNK / TCC)     // 8 points per thread
#define PRC   (PPTC / 2)        // 4 f32x2 pairs
#define NWC   (TCC / 32)        // 8 warps

typedef unsigned long long ull;

// ------------------------- device scratch (no allocs) ------------------------
__device__ __align__(16) static float4 g_pk[B_][N_];   // x,y,z,|p|^2
__device__ static float g_xs[B_][N_];
__device__ static float g_ys[B_][N_];
__device__ static float g_zs[B_][N_];
__device__ static int   g_fps[B_][M_];
__device__ static float g_FL[B_ * M_ * 64];
__device__ static float g_thr;

// ------------------------- f32x2 helpers -------------------------------------
__device__ __forceinline__ ull pack2(float a, float b) {
    ull r; asm("mov.b64 %0, {%1, %2};" : "=l"(r) : "f"(a), "f"(b)); return r;
}
__device__ __forceinline__ void unpack2(ull v, float& a, float& b) {
    asm("mov.b64 {%0, %1}, %2;" : "=f"(a), "=f"(b) : "l"(v));
}
__device__ __forceinline__ ull addx2(ull a, ull b) {
    ull r; asm("add.rn.f32x2 %0, %1, %2;" : "=l"(r) : "l"(a), "l"(b)); return r;
}
__device__ __forceinline__ ull mulx2(ull a, ull b) {
    ull r; asm("mul.rn.f32x2 %0, %1, %2;" : "=l"(r) : "l"(a), "l"(b)); return r;
}

// ------------------------- DSMEM / cluster helpers ---------------------------
__device__ __forceinline__ unsigned smem_u32(const void* p) {
    return (unsigned)__cvta_generic_to_shared(p);
}
__device__ __forceinline__ unsigned mapa_rank(unsigned laddr, unsigned rank) {
    unsigned r;
    asm("mapa.shared::cluster.u32 %0, %1, %2;" : "=r"(r) : "r"(laddr), "r"(rank));
    return r;
}
__device__ __forceinline__ void st_dsm(unsigned a, ull v) {
    asm volatile("st.shared::cluster.u64 [%0], %1;" :: "r"(a), "l"(v) : "memory");
}
__device__ __forceinline__ void st_rel_dsm(unsigned a, ull v) {
    asm volatile("st.release.cluster.shared::cluster.u64 [%0], %1;"
                 :: "r"(a), "l"(v) : "memory");
}
__device__ __forceinline__ ull ld_acq_sm(unsigned a) {
    ull v;
    asm volatile("ld.acquire.cluster.shared.u64 %0, [%1];" : "=l"(v) : "r"(a) : "memory");
    return v;
}
__device__ __forceinline__ ull ld_sm(unsigned a) {
    ull v; asm volatile("ld.shared.u64 %0, [%1];" : "=l"(v) : "r"(a) : "memory");
    return v;
}
#define CLUSTER_SYNC() do { \
    asm volatile("barrier.cluster.arrive.aligned;" ::: "memory"); \
    asm volatile("barrier.cluster.wait.aligned;"   ::: "memory"); } while (0)

// ------------------------- K1: SoA prep + norms ------------------------------
__global__ void k_prep(const float* __restrict__ xyz) {
    int i = blockIdx.x * blockDim.x + threadIdx.x;
    if (i >= B_ * N_) return;
    int b = i / N_, p = i - b * N_;
    float x = xyz[3 * i + 0], y = xyz[3 * i + 1], z = xyz[3 * i + 2];
    // matches jnp.sum(b*b,-1): ((x*x + y*y) + z*z), no fma contraction
    float n = __fadd_rn(__fadd_rn(__fmul_rn(x, x), __fmul_rn(y, y)), __fmul_rn(z, z));
    g_xs[b][p] = x; g_ys[b][p] = y; g_zs[b][p] = z;
    g_pk[b][p] = make_float4(x, y, z, n);
}

// ------------------------- K2: threshold net ---------------------------------
__global__ void k_thr(const float* __restrict__ tw1, const float* __restrict__ tb1,
                      const float* __restrict__ tw2, const float* __restrict__ tb2,
                      const float* __restrict__ tw3, const float* __restrict__ tb3) {
    __shared__ float t1s[64], t2s[64];
    int o = threadIdx.x;
    float dens = (float)(64.0 / (4.0 / 3.0 * 3.14159));   // radius 1.0
    t1s[o] = fmaxf(fmaf(dens, tw1[o], tb1[o]), 0.f);
    __syncthreads();
    float acc = tb2[o];
    #pragma unroll 8
    for (int i = 0; i < 64; i++) acc = fmaf(t1s[i], tw2[o * 64 + i], acc);
    t2s[o] = fmaxf(acc, 0.f);
    __syncthreads();
    if (o == 0) {
        float a = tb3[0];
        for (int i = 0; i < 64; i++) a = fmaf(t2s[i], tw3[i], a);
        float sg = 1.f / (1.f + expf(-a));
        g_thr = 20.f + 40.f * sg;
    }
}

// ------------------------- K3: symmetric-exchange cluster FPS ----------------
// One 8-CTA cluster per batch; CTA owns 2048 points register-resident (f32x2).
// Per iteration: local argmax (REDUX), then ONE DSMEM hop: warp0 lane l sends
// the CTA winner {xy, z, key} directly into CTA l's local slots; every CTA
// polls its OWN slots (cheap local LDS), 8-lane key-max, unique key owner
// publishes. Parity double-buffer (slots[it&1]) excludes the overwrite race:
// a CTA's it+2 same-parity write is transitively after every peer's it read.
//   key = valbits<<32 | (0xFFFFFF - gidx)<<8 | (it+1)&0xFF
// u64 max == (max value, min original idx) — exact jnp.argmax semantics.
__global__ __launch_bounds__(TCC, 1) __cluster_dims__(G_, 1, 1)
void k_fps() {
    __shared__ float sxs[CHUNK], sys[CHUNK], szs[CHUNK];   // own chunk, 24 KB
    __shared__ ull slots[2][G_][4];     // [parity][src CTA][xy, z, key, pad]
    __shared__ ull bc[3];               // winner xy, z, key
    __shared__ unsigned s_val[NWC], s_idx[NWC];

    int b   = blockIdx.x >> 3;          // cluster id (contiguous blocks)
    int g   = blockIdx.x & 7;           // rank in cluster
    int tid = threadIdx.x;
    int lane = tid & 31, wid = tid >> 5;
    unsigned base = (unsigned)g * CHUNK;

    if (tid < 2 * G_ * 4) ((ull*)slots)[tid] = 0;    // stale-SMEM guard
    for (int i = tid; i < CHUNK; i += TCC) {
        sxs[i] = g_xs[b][base + i];
        sys[i] = g_ys[b][base + i];
        szs[i] = g_zs[b][base + i];
    }
    __syncthreads();
    CLUSTER_SYNC();                     // slot zeroing visible before any send

    // register points: local p = tid + k*TCC (k=0..7), global = base + p
    ull X[PRC], Y[PRC], Z[PRC];
    float dist[PPTC];
    #pragma unroll
    for (int j = 0; j < PRC; j++) {
        int p0 = tid + (2 * j) * TCC, p1 = tid + (2 * j + 1) * TCC;
        X[j] = pack2(sxs[p0], sxs[p1]);
        Y[j] = pack2(sys[p0], sys[p1]);
        Z[j] = pack2(szs[p0], szs[p1]);
    }
    #pragma unroll
    for (int k = 0; k < PPTC; k++) dist[k] = 1e10f;

    // DSMEM send targets: warp0 lane l -> CTA l's slots[par][g]
    unsigned a_sl0 = 0, a_sl1 = 0, a_pl0 = 0, a_pl1 = 0;
    if (wid == 0 && lane < G_) {
        a_sl0 = mapa_rank(smem_u32(&slots[0][g][0]), (unsigned)lane);
        a_sl1 = mapa_rank(smem_u32(&slots[1][g][0]), (unsigned)lane);
        a_pl0 = smem_u32(&slots[0][lane][0]);        // local poll addresses
        a_pl1 = smem_u32(&slots[1][lane][0]);
    }

    float cx = g_xs[b][0], cy = g_ys[b][0], cz = g_zs[b][0];
    unsigned fidx = 0;

    for (int it = 0; it < M_; ++it) {
        if (g == 0 && tid == 0) g_fps[b][it] = (int)fidx;
        if (it == M_ - 1) break;
        unsigned tag = (unsigned)((it + 1) & 0xFF);
        int par = it & 1;

        ull ncx = pack2(-cx, -cx), ncy = pack2(-cy, -cy), ncz = pack2(-cz, -cz);
        float bv = -1.0f; unsigned bi = 0xffffffffu;
        #pragma unroll
        for (int j = 0; j < PRC; j++) {
            // x + (-c) == x - c exactly; ((dx*dx + dy*dy) + dz*dz) rn order
            ull dx = addx2(X[j], ncx);
            ull dy = addx2(Y[j], ncy);
            ull dz = addx2(Z[j], ncz);
            ull d2 = addx2(addx2(mulx2(dx, dx), mulx2(dy, dy)), mulx2(dz, dz));
            float d0, d1; unpack2(d2, d0, d1);
            float n0 = fminf(dist[2 * j], d0);     dist[2 * j] = n0;
            if (n0 > bv) { bv = n0; bi = tid + (2 * j) * TCC; }   // p asc: first max
            float n1 = fminf(dist[2 * j + 1], d1); dist[2 * j + 1] = n1;
            if (n1 > bv) { bv = n1; bi = tid + (2 * j + 1) * TCC; }
        }
        // CTA argmax (nonneg bits monotonic; ties -> min local == min global idx)
        unsigned vb = __float_as_uint(bv);
        unsigned wmax = __reduce_max_sync(FULL, vb);
        unsigned ci = (vb == wmax) ? bi : 0xffffffffu;
        unsigned wix = __reduce_min_sync(FULL, ci);
        if (lane == 0) { s_val[wid] = wmax; s_idx[wid] = wix; }
        __syncthreads();

        if (wid == 0) {
            unsigned v2 = (lane < NWC) ? s_val[lane] : 0u;
            unsigned i2 = (lane < NWC) ? s_idx[lane] : 0xffffffffu;
            unsigned m2 = __reduce_max_sync(FULL, v2);   // all lanes get result
            unsigned c2 = (v2 == m2) ? i2 : 0xffffffffu;
            unsigned f2 = __reduce_min_sync(FULL, c2);
            // one-hop all-to-all: lane l ships CTA winner to CTA l
            ull kq = 0, xy = 0, zz = 0;
            if (lane < G_) {
                float wx = sxs[f2], wy = sys[f2], wz = szs[f2];  // broadcast LDS
                ull key = ((ull)m2 << 32)
                        | ((ull)((0xFFFFFFu - (base + f2)) & 0xFFFFFFu) << 8)
                        | (ull)tag;
                unsigned as = par ? a_sl1 : a_sl0;
                st_dsm(as + 0, pack2(wx, wy));
                st_dsm(as + 8, pack2(wz, 0.f));
                st_rel_dsm(as + 16, key);                // coords ordered first
                // poll OWN slot from source CTA 'lane' (local SMEM)
                unsigned ap = par ? a_pl1 : a_pl0;
                do { kq = ld_acq_sm(ap + 16); } while ((unsigned)(kq & 0xFFu) != tag);
                xy = ld_sm(ap + 0);
                zz = ld_sm(ap + 8);
            }
            ull kw = kq;
            #pragma unroll
            for (int s = 4; s; s >>= 1) {        // lanes 8-31 carry 0, never win
                ull o = __shfl_xor_sync(FULL, kw, s);
                if (o > kw) kw = o;
            }
            if (lane < G_ && kw == kq) {         // unique owner (distinct gidx)
                bc[0] = xy; bc[1] = zz; bc[2] = kw;
            }
        }
        __syncthreads();
        float zd;
        unpack2(bc[0], cx, cy);
        unpack2(bc[1], cz, zd);
        fidx = 0xFFFFFFu - (unsigned)((bc[2] >> 8) & 0xFFFFFFu);
    }
    CLUSTER_SYNC();                     // no exit with remote stores in flight
}

// ------------------------- K4: kNN top-32 + shared MLP + masked max ----------
// 256 threads = 8 warps; warp = one centroid; SMEM point tile shared by block.
__global__ __launch_bounds__(256) void k_knn(
    const float* __restrict__ w1, const float* __restrict__ s1, const float* __restrict__ b1,
    const float* __restrict__ w2, const float* __restrict__ s2, const float* __restrict__ b2,
    const float* __restrict__ w3, const float* __restrict__ s3, const float* __restrict__ b3) {

    __shared__ float4 s_tile[2048];                       // 32 KB
    __shared__ float s_w1[96],  s_s1[32], s_b1[32];
    __shared__ float s_w2[1024], s_s2[32], s_b2[32];
    __shared__ float s_w3[2048], s_s3[64], s_b3[64];

    int tid = threadIdx.x;
    int lane = tid & 31, warp = tid >> 5;

    for (int i = tid; i < 96;   i += 256) s_w1[i] = w1[i];
    for (int i = tid; i < 1024; i += 256) s_w2[i] = w2[i];
    for (int i = tid; i < 2048; i += 256) s_w3[i] = w3[i];
    if (tid < 32) { s_s1[tid] = s1[tid]; s_b1[tid] = b1[tid];
                    s_s2[tid] = s2[tid]; s_b2[tid] = b2[tid]; }
    if (tid < 64) { s_s3[tid] = s3[tid]; s_b3[tid] = b3[tid]; }

    int b = blockIdx.x >> 9;                               // 512 blocks / batch
    int m = ((blockIdx.x & 511) << 3) + warp;
    int cidx = g_fps[b][m];
    float4 c = g_pk[b][cidx];

    const float INFP = __int_as_float(0x7f800000);
    float curmax = INFP;
    float candD  = INFP;
    int   candI  = 0x7fffff00 | lane;   // lane-unique sentinels while unfull

    for (int tile = 0; tile < 8; tile++) {
        __syncthreads();
        for (int i = tid; i < 2048; i += 256) s_tile[i] = g_pk[b][(tile << 11) + i];
        __syncthreads();
        for (int t = 0; t < 64; t++) {
            float4 p = s_tile[(t << 5) + lane];
            int pidx = (tile << 11) + (t << 5) + lane;
            // reference cdist: (an + bn) - 2*dot, no fma; clamp at 0
            float dot = __fadd_rn(__fadd_rn(__fmul_rn(c.x, p.x), __fmul_rn(c.y, p.y)),
                                  __fmul_rn(c.z, p.z));
            float d2 = fmaxf(__fsub_rn(__fadd_rn(c.w, p.w), __fmul_rn(2.f, dot)), 0.f);
            unsigned bal = __ballot_sync(FULL, d2 < curmax);
            while (bal) {
                int src = __ffs(bal) - 1;
                bal &= bal - 1;
                float dn = __shfl_sync(FULL, d2, src);
                int   in = __shfl_sync(FULL, pidx, src);
                if (dn < curmax) {               // strict < : stable top_k ties
                    unsigned db = __float_as_uint(candD);
                    unsigned mb = __reduce_max_sync(FULL, db);
                    int ei = (db == mb) ? candI : -1;
                    int me = __reduce_max_sync(FULL, ei);
                    if (db == mb && candI == me) { candD = dn; candI = in; }
                    curmax = __uint_as_float(
                        __reduce_max_sync(FULL, __float_as_uint(candD)));
                }
            }
        }
    }

    // lane = neighbor k. Mask exactly as reference: sqrt(max(d2,0)) <= 0.8
    bool msk = (__fsqrt_rn(candD) <= 0.8f);
    float4 np = g_pk[b][candI];
    float gx = __fsub_rn(np.x, c.x);
    float gy = __fsub_rn(np.y, c.y);
    float gz = __fsub_rn(np.z, c.z);

    float h1[32];
    #pragma unroll
    for (int o = 0; o < 32; o++) {
        float a = __fmul_rn(gx, s_w1[3 * o]);
        a = fmaf(gy, s_w1[3 * o + 1], a);
        a = fmaf(gz, s_w1[3 * o + 2], a);
        h1[o] = fmaxf(fmaf(a, s_s1[o], s_b1[o]), 0.f);
    }
    float h2[32];
    #pragma unroll
    for (int o = 0; o < 32; o++) {
        float acc = 0.f;
        #pragma unroll
        for (int i = 0; i < 32; i++) acc = fmaf(h1[i], s_w2[(o << 5) + i], acc);
        h2[o] = fmaxf(fmaf(acc, s_s2[o], s_b2[o]), 0.f);
    }
    const float NINF = __int_as_float(0xff800000);
    float* outFL = &g_FL[((b << 12) + m) * 64];
    for (int o = 0; o < 64; o++) {
        float acc = 0.f;
        #pragma unroll
        for (int i = 0; i < 32; i++) acc = fmaf(h2[i], s_w3[(o << 5) + i], acc);
        float v = fmaxf(fmaf(acc, s_s3[o], s_b3[o]), 0.f);
        if (!msk) v = NINF;
        #pragma unroll
        for (int s = 16; s; s >>= 1) v = fmaxf(v, __shfl_xor_sync(FULL, v, s));
        if (lane == 0) outFL[o] = v;
    }
}

// ------------------------- K5: DAM fusion ------------------------------------
__global__ __launch_bounds__(64) void k_fuse(
    const float* __restrict__ xyz, const float* __restrict__ pts_cam,
    const float* __restrict__ FI,
    const float* __restrict__ gw_raw, const float* __restrict__ gb_raw,
    const float* __restrict__ gw_img, const float* __restrict__ gb_img,
    const float* __restrict__ gw_lid, const float* __restrict__ gb_lid,
    const float* __restrict__ uw, const float* __restrict__ ub,
    const float* __restrict__ vw, const float* __restrict__ vb,
    float* __restrict__ out) {

    __shared__ float sFI[64], sFL[64], sPI[64], sPV[64], sW[2];
    int h = threadIdx.x;
    int g = blockIdx.x;
    int b = g >> 12, m = g & 4095;
    int idx = g_fps[b][m];

    sFI[h] = FI[((b << 6) + h) * N_ + idx];
    sFL[h] = g_FL[((b << 12) + m) * 64 + h];
    __syncthreads();

    float x0 = xyz[(b * N_ + idx) * 3 + 0];
    float x1 = xyz[(b * N_ + idx) * 3 + 1];
    float x2 = xyz[(b * N_ + idx) * 3 + 2];

    float fr = gb_raw[h];
    fr = fmaf(x0, gw_raw[3 * h + 0], fr);
    fr = fmaf(x1, gw_raw[3 * h + 1], fr);
    fr = fmaf(x2, gw_raw[3 * h + 2], fr);
    fr = fmaxf(fr, 0.f);

    float fi = gb_img[h], fl = gb_lid[h];
    #pragma unroll 8
    for (int i = 0; i < 64; i++) {
        fi = fmaf(sFI[i], gw_img[(h << 6) + i], fi);
        fl = fmaf(sFL[i], gw_lid[(h << 6) + i], fl);
    }
    fi = fmaxf(fi, 0.f);
    fl = fmaxf(fl, 0.f);

    float s = tanhf(fr + fi + fl);
    sPI[h] = s * uw[h];
    sPV[h] = s * vw[h];
    __syncthreads();
    if (h == 0) {
        float aI = ub[0], aV = vb[0];
        for (int i = 0; i < 64; i++) { aI += sPI[i]; aV += sPV[i]; }
        sW[0] = 1.f / (1.f + expf(-aI));
        sW[1] = 1.f / (1.f + expf(-aV));
    }
    __syncthreads();
    float wI = sW[0], wL = sW[1];

    float z = pts_cam[(b * N_ + idx) * 3 + 2];
    bool near = (z <= g_thr);
    float o1 = near ? sFL[h] : sFI[h];
    float o2 = near ? sFI[h] * wI : sFL[h] * wL;
    out[((b << 7) + h) * M_ + m]        = o1;
    out[((b << 7) + 64 + h) * M_ + m]   = o2;
}

// ------------------------- launch --------------------------------------------
extern "C" void kernel_launch(void* const* d_in, const int* in_sizes, int n_in,
                              void* d_out, int out_size) {
    const float* xyz     = (const float*)d_in[0];
    const float* pts_cam = (const float*)d_in[1];
    const float* FI      = (const float*)d_in[2];
    const float* w1 = (const float*)d_in[3];
    const float* s1 = (const float*)d_in[4];
    const float* b1 = (const float*)d_in[5];
    const float* w2 = (const float*)d_in[6];
    const float* s2 = (const float*)d_in[7];
    const float* b2 = (const float*)d_in[8];
    const float* w3 = (const float*)d_in[9];
    const float* s3 = (const float*)d_in[10];
    const float* b3 = (const float*)d_in[11];
    const float* tw1 = (const float*)d_in[12];
    const float* tb1 = (const float*)d_in[13];
    const float* tw2 = (const float*)d_in[14];
    const float* tb2 = (const float*)d_in[15];
    const float* tw3 = (const float*)d_in[16];
    const float* tb3 = (const float*)d_in[17];
    const float* gw_raw = (const float*)d_in[18];
    const float* gb_raw = (const float*)d_in[19];
    const float* gw_img = (const float*)d_in[20];
    const float* gb_img = (const float*)d_in[21];
    const float* gw_lid = (const float*)d_in[22];
    const float* gb_lid = (const float*)d_in[23];
    const float* uw = (const float*)d_in[24];
    const float* ub = (const float*)d_in[25];
    const float* vw = (const float*)d_in[26];
    const float* vb = (const float*)d_in[27];
    float* out = (float*)d_out;

    k_prep<<<(B_ * N_ + 255) / 256, 256>>>(xyz);
    k_thr<<<1, 64>>>(tw1, tb1, tw2, tb2, tw3, tb3);

    k_fps<<<B_ * G_, TCC>>>();

    k_knn<<<(B_ * M_) / 8, 256>>>(w1, s1, b1, w2, s2, b2, w3, s3, b3);
    k_fuse<<<B_ * M_, 64>>>(xyz, pts_cam, FI,
                            gw_raw, gb_raw, gw_img, gb_img, gw_lid, gb_lid,
                            uw, ub, vw, vb, out);
}

// round 15
// speedup vs baseline: 2.5380x; 2.5380x over previous
#include <cuda_runtime.h>
#include <math.h>

#define B_   2
#define N_   16384
#define M_   4096
#define KG_  32
#define FULL 0xffffffffu

#define G_    8                 // FPS CTAs per cluster (one cluster per batch)
#define TCC   512               // threads per FPS CTA
#define CHUNK (N_ / G_)         // 2048 points owned per CTA
#define PPTC  (CHUNK / TCC)     // 4 points per thread
#define PRC   (PPTC / 2)        // 2 f32x2 pairs
#define NWC   (TCC / 32)        // 16 warps

typedef unsigned long long ull;

// ------------------------- device scratch (no allocs) ------------------------
__device__ __align__(16) static float4 g_pk[B_][N_];   // x,y,z,|p|^2
__device__ static float g_xs[B_][N_];
__device__ static float g_ys[B_][N_];
__device__ static float g_zs[B_][N_];
__device__ static int   g_fps[B_][M_];
__device__ static float g_FL[B_ * M_ * 64];
__device__ static float g_thr;

// ------------------------- f32x2 helpers -------------------------------------
__device__ __forceinline__ ull pack2(float a, float b) {
    ull r; asm("mov.b64 %0, {%1, %2};" : "=l"(r) : "f"(a), "f"(b)); return r;
}
__device__ __forceinline__ void unpack2(ull v, float& a, float& b) {
    asm("mov.b64 {%0, %1}, %2;" : "=f"(a), "=f"(b) : "l"(v));
}
__device__ __forceinline__ ull addx2(ull a, ull b) {
    ull r; asm("add.rn.f32x2 %0, %1, %2;" : "=l"(r) : "l"(a), "l"(b)); return r;
}
__device__ __forceinline__ ull mulx2(ull a, ull b) {
    ull r; asm("mul.rn.f32x2 %0, %1, %2;" : "=l"(r) : "l"(a), "l"(b)); return r;
}

// ------------------------- DSMEM helpers (relaxed, NO fences) ----------------
__device__ __forceinline__ unsigned smem_u32(const void* p) {
    return (unsigned)__cvta_generic_to_shared(p);
}
__device__ __forceinline__ unsigned mapa_rank(unsigned laddr, unsigned rank) {
    unsigned r;
    asm("mapa.shared::cluster.u32 %0, %1, %2;" : "=r"(r) : "r"(laddr), "r"(rank));
    return r;
}
// single-u64 message: atomicity of one word + embedded tag = no ordering needed
__device__ __forceinline__ void st_rlx_dsm(unsigned a, ull v) {
    asm volatile("st.relaxed.cluster.shared::cluster.u64 [%0], %1;"
                 :: "r"(a), "l"(v) : "memory");
}
__device__ __forceinline__ ull ld_rlx_sm(unsigned a) {
    ull v;
    asm volatile("ld.relaxed.cluster.shared::cta.u64 %0, [%1];"
                 : "=l"(v) : "r"(a) : "memory");
    return v;
}
#define CLUSTER_SYNC() do { \
    asm volatile("barrier.cluster.arrive.aligned;" ::: "memory"); \
    asm volatile("barrier.cluster.wait.aligned;"   ::: "memory"); } while (0)

// ------------------------- K1: SoA prep + norms ------------------------------
__global__ void k_prep(const float* __restrict__ xyz) {
    int i = blockIdx.x * blockDim.x + threadIdx.x;
    if (i >= B_ * N_) return;
    int b = i / N_, p = i - b * N_;
    float x = xyz[3 * i + 0], y = xyz[3 * i + 1], z = xyz[3 * i + 2];
    // matches jnp.sum(b*b,-1): ((x*x + y*y) + z*z), no fma contraction
    float n = __fadd_rn(__fadd_rn(__fmul_rn(x, x), __fmul_rn(y, y)), __fmul_rn(z, z));
    g_xs[b][p] = x; g_ys[b][p] = y; g_zs[b][p] = z;
    g_pk[b][p] = make_float4(x, y, z, n);
}

// ------------------------- K2: threshold net ---------------------------------
__global__ void k_thr(const float* __restrict__ tw1, const float* __restrict__ tb1,
                      const float* __restrict__ tw2, const float* __restrict__ tb2,
                      const float* __restrict__ tw3, const float* __restrict__ tb3) {
    __shared__ float t1s[64], t2s[64];
    int o = threadIdx.x;
    float dens = (float)(64.0 / (4.0 / 3.0 * 3.14159));   // radius 1.0
    t1s[o] = fmaxf(fmaf(dens, tw1[o], tb1[o]), 0.f);
    __syncthreads();
    float acc = tb2[o];
    #pragma unroll 8
    for (int i = 0; i < 64; i++) acc = fmaf(t1s[i], tw2[o * 64 + i], acc);
    t2s[o] = fmaxf(acc, 0.f);
    __syncthreads();
    if (o == 0) {
        float a = tb3[0];
        for (int i = 0; i < 64; i++) a = fmaf(t2s[i], tw3[i], a);
        float sg = 1.f / (1.f + expf(-a));
        g_thr = 20.f + 40.f * sg;
    }
}

// ------------------------- K3: fence-free cluster FPS ------------------------
// 8-CTA cluster per batch. Each CTA: full cloud in SMEM (192KB, for winner
// coord lookup) + OWN 2048 points register-resident (f32x2) + dist in regs.
// Per iteration, after the local REDUX argmax, warp0 lane l ships ONE u64
//   key = valbits<<32 | (0xFFFFFF - gidx)<<8 | (it+1)&0xFF
// via st.relaxed straight into CTA l's slots[par][g]; every CTA polls its OWN
// slots with ld.relaxed (plain LDS speed, no acquire), 8-lane shfl max, then
// reads winner coords from its own SMEM cloud. Single-word messages need no
// release/acquire: word atomicity + tag validate them. Parity double-buffer
// kills the overwrite race (it+2 same-parity send transitively happens-after
// every peer's it read). u64 max == (max val, min orig idx) == jnp.argmax.
__global__ __launch_bounds__(TCC, 1) __cluster_dims__(G_, 1, 1)
void k_fps() {
    extern __shared__ float sm[];
    float* sx = sm;
    float* sy = sm + N_;
    float* sz = sm + 2 * N_;
    __shared__ ull slots[2][G_];
    __shared__ ull s_win;
    __shared__ unsigned s_val[NWC], s_idx[NWC];

    int b   = blockIdx.x >> 3;          // cluster id (contiguous blocks)
    int g   = blockIdx.x & 7;           // rank in cluster
    int tid = threadIdx.x;
    int lane = tid & 31, wid = tid >> 5;
    unsigned base = (unsigned)g * CHUNK;

    if (tid < 2 * G_) ((ull*)slots)[tid] = 0;      // stale-SMEM guard
    for (int i = tid; i < N_; i += TCC) {          // full cloud copy
        sx[i] = g_xs[b][i]; sy[i] = g_ys[b][i]; sz[i] = g_zs[b][i];
    }
    __syncthreads();
    CLUSTER_SYNC();                     // zeroed slots visible before any send

    // own chunk register-resident: local p = tid + k*TCC (k=0..3)
    ull X[PRC], Y[PRC], Z[PRC];
    float dist[PPTC];
    #pragma unroll
    for (int j = 0; j < PRC; j++) {
        int p0 = base + tid + (2 * j) * TCC;
        int p1 = base + tid + (2 * j + 1) * TCC;
        X[j] = pack2(sx[p0], sx[p1]);
        Y[j] = pack2(sy[p0], sy[p1]);
        Z[j] = pack2(sz[p0], sz[p1]);
    }
    #pragma unroll
    for (int k = 0; k < PPTC; k++) dist[k] = 1e10f;

    // exchange addresses: lane l sends to CTA l's slots[par][g]; polls own [par][l]
    unsigned a_s0 = 0, a_s1 = 0, a_p0 = 0, a_p1 = 0;
    if (wid == 0 && lane < G_) {
        a_s0 = mapa_rank(smem_u32(&slots[0][g]), (unsigned)lane);
        a_s1 = mapa_rank(smem_u32(&slots[1][g]), (unsigned)lane);
        a_p0 = smem_u32(&slots[0][lane]);
        a_p1 = smem_u32(&slots[1][lane]);
    }

    float cx = sx[0], cy = sy[0], cz = sz[0];      // first centroid = orig 0
    unsigned fidx = 0;

    for (int it = 0; it < M_; ++it) {
        if (g == 0 && tid == 0) g_fps[b][it] = (int)fidx;
        if (it == M_ - 1) break;
        unsigned tag = (unsigned)((it + 1) & 0xFF);
        int par = it & 1;

        ull ncx = pack2(-cx, -cx), ncy = pack2(-cy, -cy), ncz = pack2(-cz, -cz);
        float bv = -1.0f; unsigned bi = 0xffffffffu;
        #pragma unroll
        for (int j = 0; j < PRC; j++) {
            // x + (-c) == x - c exactly; ((dx*dx + dy*dy) + dz*dz) rn order
            ull dx = addx2(X[j], ncx);
            ull dy = addx2(Y[j], ncy);
            ull dz = addx2(Z[j], ncz);
            ull d2 = addx2(addx2(mulx2(dx, dx), mulx2(dy, dy)), mulx2(dz, dz));
            float d0, d1; unpack2(d2, d0, d1);
            float n0 = fminf(dist[2 * j], d0);     dist[2 * j] = n0;
            if (n0 > bv) { bv = n0; bi = base + tid + (2 * j) * TCC; }
            float n1 = fminf(dist[2 * j + 1], d1); dist[2 * j + 1] = n1;
            if (n1 > bv) { bv = n1; bi = base + tid + (2 * j + 1) * TCC; }
        }
        // CTA argmax (nonneg bits monotonic; ties -> min global idx)
        unsigned vb = __float_as_uint(bv);
        unsigned wmax = __reduce_max_sync(FULL, vb);
        unsigned ci = (vb == wmax) ? bi : 0xffffffffu;
        unsigned wix = __reduce_min_sync(FULL, ci);
        if (lane == 0) { s_val[wid] = wmax; s_idx[wid] = wix; }
        __syncthreads();

        if (wid == 0) {
            unsigned v2 = (lane < NWC) ? s_val[lane] : 0u;
            unsigned i2 = (lane < NWC) ? s_idx[lane] : 0xffffffffu;
            unsigned m2 = __reduce_max_sync(FULL, v2);
            unsigned c2 = (v2 == m2) ? i2 : 0xffffffffu;
            unsigned f2 = __reduce_min_sync(FULL, c2);
            ull kq = 0;
            if (lane < G_) {
                ull key = ((ull)m2 << 32)
                        | ((ull)((0xFFFFFFu - f2) & 0xFFFFFFu) << 8)
                        | (ull)tag;
                st_rlx_dsm(par ? a_s1 : a_s0, key);        // one-hop send
                unsigned ap = par ? a_p1 : a_p0;           // local poll (LDS)
                do { kq = ld_rlx_sm(ap); } while ((unsigned)(kq & 0xFFu) != tag);
            }
            #pragma unroll
            for (int s = 4; s; s >>= 1) {      // lanes 8-31 carry 0, never win
                ull o = __shfl_xor_sync(FULL, kq, s);
                if (o > kq) kq = o;
            }
            if (lane == 0) s_win = kq;
        }
        __syncthreads();
        ull kw = s_win;
        fidx = 0xFFFFFFu - (unsigned)((kw >> 8) & 0xFFFFFFu);
        cx = sx[fidx]; cy = sy[fidx]; cz = sz[fidx];   // broadcast LDS
    }
    CLUSTER_SYNC();                     // no exit with remote stores in flight
}

// ------------------------- K4: kNN top-32 + shared MLP + masked max ----------
// 256 threads = 8 warps; warp = one centroid; SMEM point tile shared by block.
__global__ __launch_bounds__(256) void k_knn(
    const float* __restrict__ w1, const float* __restrict__ s1, const float* __restrict__ b1,
    const float* __restrict__ w2, const float* __restrict__ s2, const float* __restrict__ b2,
    const float* __restrict__ w3, const float* __restrict__ s3, const float* __restrict__ b3) {

    __shared__ float4 s_tile[2048];                       // 32 KB
    __shared__ float s_w1[96],  s_s1[32], s_b1[32];
    __shared__ float s_w2[1024], s_s2[32], s_b2[32];
    __shared__ float s_w3[2048], s_s3[64], s_b3[64];

    int tid = threadIdx.x;
    int lane = tid & 31, warp = tid >> 5;

    for (int i = tid; i < 96;   i += 256) s_w1[i] = w1[i];
    for (int i = tid; i < 1024; i += 256) s_w2[i] = w2[i];
    for (int i = tid; i < 2048; i += 256) s_w3[i] = w3[i];
    if (tid < 32) { s_s1[tid] = s1[tid]; s_b1[tid] = b1[tid];
                    s_s2[tid] = s2[tid]; s_b2[tid] = b2[tid]; }
    if (tid < 64) { s_s3[tid] = s3[tid]; s_b3[tid] = b3[tid]; }

    int b = blockIdx.x >> 9;                               // 512 blocks / batch
    int m = ((blockIdx.x & 511) << 3) + warp;
    int cidx = g_fps[b][m];
    float4 c = g_pk[b][cidx];

    const float INFP = __int_as_float(0x7f800000);
    float curmax = INFP;
    float candD  = INFP;
    int   candI  = 0x7fffff00 | lane;   // lane-unique sentinels while unfull

    for (int tile = 0; tile < 8; tile++) {
        __syncthreads();
        for (int i = tid; i < 2048; i += 256) s_tile[i] = g_pk[b][(tile << 11) + i];
        __syncthreads();
        for (int t = 0; t < 64; t++) {
            float4 p = s_tile[(t << 5) + lane];
            int pidx = (tile << 11) + (t << 5) + lane;
            // reference cdist: (an + bn) - 2*dot, no fma; clamp at 0
            float dot = __fadd_rn(__fadd_rn(__fmul_rn(c.x, p.x), __fmul_rn(c.y, p.y)),
                                  __fmul_rn(c.z, p.z));
            float d2 = fmaxf(__fsub_rn(__fadd_rn(c.w, p.w), __fmul_rn(2.f, dot)), 0.f);
            unsigned bal = __ballot_sync(FULL, d2 < curmax);
            while (bal) {
                int src = __ffs(bal) - 1;
                bal &= bal - 1;
                float dn = __shfl_sync(FULL, d2, src);
                int   in = __shfl_sync(FULL, pidx, src);
                if (dn < curmax) {               // strict < : stable top_k ties
                    unsigned db = __float_as_uint(candD);
                    unsigned mb = __reduce_max_sync(FULL, db);
                    int ei = (db == mb) ? candI : -1;
                    int me = __reduce_max_sync(FULL, ei);
                    if (db == mb && candI == me) { candD = dn; candI = in; }
                    curmax = __uint_as_float(
                        __reduce_max_sync(FULL, __float_as_uint(candD)));
                }
            }
        }
    }

    // lane = neighbor k. Mask exactly as reference: sqrt(max(d2,0)) <= 0.8
    bool msk = (__fsqrt_rn(candD) <= 0.8f);
    float4 np = g_pk[b][candI];
    float gx = __fsub_rn(np.x, c.x);
    float gy = __fsub_rn(np.y, c.y);
    float gz = __fsub_rn(np.z, c.z);

    float h1[32];
    #pragma unroll
    for (int o = 0; o < 32; o++) {
        float a = __fmul_rn(gx, s_w1[3 * o]);
        a = fmaf(gy, s_w1[3 * o + 1], a);
        a = fmaf(gz, s_w1[3 * o + 2], a);
        h1[o] = fmaxf(fmaf(a, s_s1[o], s_b1[o]), 0.f);
    }
    float h2[32];
    #pragma unroll
    for (int o = 0; o < 32; o++) {
        float acc = 0.f;
        #pragma unroll
        for (int i = 0; i < 32; i++) acc = fmaf(h1[i], s_w2[(o << 5) + i], acc);
        h2[o] = fmaxf(fmaf(acc, s_s2[o], s_b2[o]), 0.f);
    }
    const float NINF = __int_as_float(0xff800000);
    float* outFL = &g_FL[((b << 12) + m) * 64];
    for (int o = 0; o < 64; o++) {
        float acc = 0.f;
        #pragma unroll
        for (int i = 0; i < 32; i++) acc = fmaf(h2[i], s_w3[(o << 5) + i], acc);
        float v = fmaxf(fmaf(acc, s_s3[o], s_b3[o]), 0.f);
        if (!msk) v = NINF;
        #pragma unroll
        for (int s = 16; s; s >>= 1) v = fmaxf(v, __shfl_xor_sync(FULL, v, s));
        if (lane == 0) outFL[o] = v;
    }
}

// ------------------------- K5: DAM fusion ------------------------------------
__global__ __launch_bounds__(64) void k_fuse(
    const float* __restrict__ xyz, const float* __restrict__ pts_cam,
    const float* __restrict__ FI,
    const float* __restrict__ gw_raw, const float* __restrict__ gb_raw,
    const float* __restrict__ gw_img, const float* __restrict__ gb_img,
    const float* __restrict__ gw_lid, const float* __restrict__ gb_lid,
    const float* __restrict__ uw, const float* __restrict__ ub,
    const float* __restrict__ vw, const float* __restrict__ vb,
    float* __restrict__ out) {

    __shared__ float sFI[64], sFL[64], sPI[64], sPV[64], sW[2];
    int h = threadIdx.x;
    int g = blockIdx.x;
    int b = g >> 12, m = g & 4095;
    int idx = g_fps[b][m];

    sFI[h] = FI[((b << 6) + h) * N_ + idx];
    sFL[h] = g_FL[((b << 12) + m) * 64 + h];
    __syncthreads();

    float x0 = xyz[(b * N_ + idx) * 3 + 0];
    float x1 = xyz[(b * N_ + idx) * 3 + 1];
    float x2 = xyz[(b * N_ + idx) * 3 + 2];

    float fr = gb_raw[h];
    fr = fmaf(x0, gw_raw[3 * h + 0], fr);
    fr = fmaf(x1, gw_raw[3 * h + 1], fr);
    fr = fmaf(x2, gw_raw[3 * h + 2], fr);
    fr = fmaxf(fr, 0.f);

    float fi = gb_img[h], fl = gb_lid[h];
    #pragma unroll 8
    for (int i = 0; i < 64; i++) {
        fi = fmaf(sFI[i], gw_img[(h << 6) + i], fi);
        fl = fmaf(sFL[i], gw_lid[(h << 6) + i], fl);
    }
    fi = fmaxf(fi, 0.f);
    fl = fmaxf(fl, 0.f);

    float s = tanhf(fr + fi + fl);
    sPI[h] = s * uw[h];
    sPV[h] = s * vw[h];
    __syncthreads();
    if (h == 0) {
        float aI = ub[0], aV = vb[0];
        for (int i = 0; i < 64; i++) { aI += sPI[i]; aV += sPV[i]; }
        sW[0] = 1.f / (1.f + expf(-aI));
        sW[1] = 1.f / (1.f + expf(-aV));
    }
    __syncthreads();
    float wI = sW[0], wL = sW[1];

    float z = pts_cam[(b * N_ + idx) * 3 + 2];
    bool near = (z <= g_thr);
    float o1 = near ? sFL[h] : sFI[h];
    float o2 = near ? sFI[h] * wI : sFL[h] * wL;
    out[((b << 7) + h) * M_ + m]        = o1;
    out[((b << 7) + 64 + h) * M_ + m]   = o2;
}

// ------------------------- launch --------------------------------------------
extern "C" void kernel_launch(void* const* d_in, const int* in_sizes, int n_in,
                              void* d_out, int out_size) {
    const float* xyz     = (const float*)d_in[0];
    const float* pts_cam = (const float*)d_in[1];
    const float* FI      = (const float*)d_in[2];
    const float* w1 = (const float*)d_in[3];
    const float* s1 = (const float*)d_in[4];
    const float* b1 = (const float*)d_in[5];
    const float* w2 = (const float*)d_in[6];
    const float* s2 = (const float*)d_in[7];
    const float* b2 = (const float*)d_in[8];
    const float* w3 = (const float*)d_in[9];
    const float* s3 = (const float*)d_in[10];
    const float* b3 = (const float*)d_in[11];
    const float* tw1 = (const float*)d_in[12];
    const float* tb1 = (const float*)d_in[13];
    const float* tw2 = (const float*)d_in[14];
    const float* tb2 = (const float*)d_in[15];
    const float* tw3 = (const float*)d_in[16];
    const float* tb3 = (const float*)d_in[17];
    const float* gw_raw = (const float*)d_in[18];
    const float* gb_raw = (const float*)d_in[19];
    const float* gw_img = (const float*)d_in[20];
    const float* gb_img = (const float*)d_in[21];
    const float* gw_lid = (const float*)d_in[22];
    const float* gb_lid = (const float*)d_in[23];
    const float* uw = (const float*)d_in[24];
    const float* ub = (const float*)d_in[25];
    const float* vw = (const float*)d_in[26];
    const float* vb = (const float*)d_in[27];
    float* out = (float*)d_out;

    k_prep<<<(B_ * N_ + 255) / 256, 256>>>(xyz);
    k_thr<<<1, 64>>>(tw1, tb1, tw2, tb2, tw3, tb3);

    cudaFuncSetAttribute(k_fps, cudaFuncAttributeMaxDynamicSharedMemorySize,
                         3 * N_ * (int)sizeof(float));
    k_fps<<<B_ * G_, TCC, 3 * N_ * sizeof(float)>>>();

    k_knn<<<(B_ * M_) / 8, 256>>>(w1, s1, b1, w2, s2, b2, w3, s3, b3);
    k_fuse<<<B_ * M_, 64>>>(xyz, pts_cam, FI,
                            gw_raw, gb_raw, gw_img, gb_img, gw_lid, gb_lid,
                            uw, ub, vw, vb, out);
}